// round 5
// baseline (speedup 1.0000x reference)
#include <cuda_runtime.h>
#include <cstdint>

#define NROWS 1024
#define DF    12
#define NMASK 4096          // 2^D
#define KSEL  32
#define NCLS  10

// Scratch (no cudaMalloc allowed)
__device__ float g_cap_lookup[NMASK];     // cap_lookup[mask], [0]=0
__device__ float g_partial[32][16];       // per-block h3 partial sums
__device__ float g_sims[NROWS * NROWS];   // full similarity matrix (4MB)

// ---------------------------------------------------------------------------
// Kernel 1: encoder MLP. 32 blocks x 32 threads, 1 row/thread.
// ---------------------------------------------------------------------------
__global__ void __launch_bounds__(32, 1)
enc_kernel(const float* __restrict__ X,
           const float* __restrict__ w1, const float* __restrict__ b1,
           const float* __restrict__ w2, const float* __restrict__ b2,
           const float* __restrict__ lng, const float* __restrict__ lnb,
           const float* __restrict__ w3, const float* __restrict__ b3)
{
    const int lane = threadIdx.x;
    const int row  = blockIdx.x * 32 + lane;

    const float4* xr = (const float4*)(X + row * DF);
    float4 x0 = xr[0], x1 = xr[1], x2 = xr[2];

    float h1[32];
#pragma unroll
    for (int o = 0; o < 32; o++) {
        const float4* wr = (const float4*)(w1 + o * DF);
        float4 a0 = wr[0], a1 = wr[1], a2 = wr[2];
        float a = b1[o];
        a = fmaf(x0.x, a0.x, a); a = fmaf(x0.y, a0.y, a);
        a = fmaf(x0.z, a0.z, a); a = fmaf(x0.w, a0.w, a);
        a = fmaf(x1.x, a1.x, a); a = fmaf(x1.y, a1.y, a);
        a = fmaf(x1.z, a1.z, a); a = fmaf(x1.w, a1.w, a);
        a = fmaf(x2.x, a2.x, a); a = fmaf(x2.y, a2.y, a);
        a = fmaf(x2.z, a2.z, a); a = fmaf(x2.w, a2.w, a);
        h1[o] = fmaxf(a, 0.0f);
    }

    float h2[16];
#pragma unroll
    for (int o = 0; o < 16; o++) {
        const float4* wr = (const float4*)(w2 + o * 32);
        float a = b2[o];
#pragma unroll
        for (int q = 0; q < 8; q++) {
            float4 v = wr[q];
            a = fmaf(h1[q*4+0], v.x, a);
            a = fmaf(h1[q*4+1], v.y, a);
            a = fmaf(h1[q*4+2], v.z, a);
            a = fmaf(h1[q*4+3], v.w, a);
        }
        h2[o] = fmaxf(a, 0.0f);
    }

    float mu = 0.0f;
#pragma unroll
    for (int o = 0; o < 16; o++) mu += h2[o];
    mu *= (1.0f/16.0f);
    float var = 0.0f;
#pragma unroll
    for (int o = 0; o < 16; o++) { float dd = h2[o] - mu; var = fmaf(dd, dd, var); }
    var *= (1.0f/16.0f);
    float rs = rsqrtf(var + 1e-5f);
    float hn[16];
#pragma unroll
    for (int o = 0; o < 16; o++) hn[o] = fmaf((h2[o]-mu)*rs, lng[o], lnb[o]);

#pragma unroll
    for (int o = 0; o < 16; o++) {
        const float4* wr = (const float4*)(w3 + o * 16);
        float a = b3[o];
#pragma unroll
        for (int q = 0; q < 4; q++) {
            float4 v = wr[q];
            a = fmaf(hn[q*4+0], v.x, a);
            a = fmaf(hn[q*4+1], v.y, a);
            a = fmaf(hn[q*4+2], v.z, a);
            a = fmaf(hn[q*4+3], v.w, a);
        }
#pragma unroll
        for (int off = 16; off; off >>= 1) a += __shfl_xor_sync(0xffffffffu, a, off);
        if (lane == 0) g_partial[blockIdx.x][o] = a;
    }
}

// ---------------------------------------------------------------------------
// Kernel 2 (fused incr + zeta): latent -> hc -> increments -> subset-sum
// zeta transform -> normalized cap_lookup + caps output. 1 block x 1024 thr.
// ---------------------------------------------------------------------------
__global__ void __launch_bounds__(1024, 1)
capgen_kernel(const float* __restrict__ cw1, const float* __restrict__ cb1,
              const float* __restrict__ cw2, const float* __restrict__ cb2,
              float* __restrict__ out)
{
    __shared__ float g[NMASK];
    __shared__ float lat[16], hc[16];
    const int tid = threadIdx.x;

    if (tid < 16) {
        float s = 0.0f;
#pragma unroll
        for (int b = 0; b < 32; b++) s += g_partial[b][tid];
        lat[tid] = s * (1.0f/1024.0f);
    }
    __syncthreads();
    if (tid < 16) {
        float a = cb1[tid];
#pragma unroll
        for (int f = 0; f < 16; f++) a = fmaf(lat[f], cw1[tid*16 + f], a);
        hc[tid] = fmaxf(a, 0.0f);
    }
    __syncthreads();

    // increments: 4 masks per thread (coalesced 256KB cw2 read)
#pragma unroll
    for (int t = 0; t < 4; t++) {
        int m = t * 1024 + tid;
        if (m >= 1) {
            int r = m - 1;
            const float4* wr = (const float4*)(cw2 + r*16);
            float4 a0 = wr[0], a1 = wr[1], a2 = wr[2], a3 = wr[3];
            float z = cb2[r];
            z = fmaf(a0.x, hc[0],  z); z = fmaf(a0.y, hc[1],  z);
            z = fmaf(a0.z, hc[2],  z); z = fmaf(a0.w, hc[3],  z);
            z = fmaf(a1.x, hc[4],  z); z = fmaf(a1.y, hc[5],  z);
            z = fmaf(a1.z, hc[6],  z); z = fmaf(a1.w, hc[7],  z);
            z = fmaf(a2.x, hc[8],  z); z = fmaf(a2.y, hc[9],  z);
            z = fmaf(a2.z, hc[10], z); z = fmaf(a2.w, hc[11], z);
            z = fmaf(a3.x, hc[12], z); z = fmaf(a3.y, hc[13], z);
            z = fmaf(a3.z, hc[14], z); z = fmaf(a3.w, hc[15], z);
            g[m] = 0.1f / (1.0f + __expf(-z));
        } else {
            g[0] = 0.0f;
        }
    }
    __syncthreads();

    // subset-sum (zeta) transform: g[m] = sum_{b subset m} inc[b]
#pragma unroll
    for (int bit = 0; bit < DF; bit++) {
#pragma unroll
        for (int t = 0; t < 2; t++) {
            int i = t * 1024 + tid;
            int low = i & ((1 << bit) - 1);
            int m = ((i >> bit) << (bit + 1)) | (1 << bit) | low;
            g[m] += g[m ^ (1 << bit)];
        }
        __syncthreads();
    }

    float nrm = g[NMASK-1] + 1e-8f;
#pragma unroll
    for (int t = 0; t < 4; t++) {
        int m = t * 1024 + tid;
        float c = g[m] / nrm;
        g_cap_lookup[m] = c;
        if (m >= 1) out[NROWS*NCLS + m - 1] = c;   // caps output (S=4095)
    }
}

// ---------------------------------------------------------------------------
// Kernel 3: symmetric Choquet tiles. 528 blocks (upper-tri 32x32 tiles) x 512.
// Each thread computes 2 pairs; tile staged in padded smem, both the tile and
// its transpose written coalesced to g_sims.
// ---------------------------------------------------------------------------
__global__ void __launch_bounds__(512, 3)
sym_kernel(const float* __restrict__ X)
{
    __shared__ float caps[NMASK];
    __shared__ float xiT[DF][33];    // xiT[d][row-in-I-tile]
    __shared__ float xjT[DF][33];    // xjT[d][row-in-J-tile]
    __shared__ float tile[32][33];

    const int tid  = threadIdx.x;
    const int lane = tid & 31, w = tid >> 5;   // w in [0,16)

    // triangular decode: blockIdx -> (I >= J)
    int b = blockIdx.x;
    int I = (int)((sqrtf(8.0f * (float)b + 1.0f) - 1.0f) * 0.5f);
    if (I * (I + 1) / 2 > b) I--;
    if ((I + 1) * (I + 2) / 2 <= b) I++;
    int J = b - I * (I + 1) / 2;

    // caps -> smem (4096 floats = 2 float4/thread)
    {
        const float4* src = (const float4*)g_cap_lookup;
        float4* dst = (float4*)caps;
        dst[tid]       = src[tid];
        dst[tid + 512] = src[tid + 512];
    }
    // X tiles transposed into smem (coalesced LDG, scattered STS)
    if (tid < 384) {
        int r = tid / DF, d = tid - r * DF;
        xiT[d][r] = X[(I * 32 + r) * DF + d];
        xjT[d][r] = X[(J * 32 + r) * DF + d];
    }
    __syncthreads();

    // j-row for this lane cached in registers across both sub-rows
    const int j = J * 32 + lane;
    float pj[DF];
#pragma unroll
    for (int d = 0; d < DF; d++) pj[d] = xjT[d][lane];

#pragma unroll
    for (int q = 0; q < 2; q++) {
        const int il = w + 16 * q;
        const int i  = I * 32 + il;
        float sim;
        if (i == j) {
            sim = -1e9f;                     // exclude self
        } else {
            // keys: |diff| float bits (monotone; 0x7FFFFFF0 clears sign+low), id in low 4
            unsigned k[DF];
#pragma unroll
            for (int d = 0; d < DF; d++) {
                float diff = pj[d] - xiT[d][il];   // xiT broadcast (il warp-uniform)
                k[d] = (__float_as_uint(diff) & 0x7FFFFFF0u) | (unsigned)d;
            }
            // Batcher odd-even mergesort (descending), ~41 comparators for n=12
#pragma unroll
            for (int p = 1; p < DF; p <<= 1) {
#pragma unroll
                for (int kk = p; kk >= 1; kk >>= 1) {
#pragma unroll
                    for (int jj = kk % p; jj <= DF - 1 - kk; jj += 2 * kk) {
#pragma unroll
                        for (int ii = 0; ii < kk; ii++) {
                            int a = ii + jj, c = ii + jj + kk;
                            if (c < DF && (a / (2 * p)) == (c / (2 * p))) {
                                unsigned lo = umin(k[a], k[c]);
                                unsigned hi = umax(k[a], k[c]);
                                k[a] = hi; k[c] = lo;
                            }
                        }
                    }
                }
            }
            // Choquet: sum_p (v_p - v_{p-1}) * cap[suffix_mask_p]
            float prev = 0.0f; sim = 0.0f;
            unsigned mask = (unsigned)(NMASK - 1);
#pragma unroll
            for (int p = 0; p < DF; p++) {
                float dpos = __uint_as_float(k[p] & 0xFFFFFFF0u);
                float v = __expf(-dpos);
                sim = fmaf(v - prev, caps[mask], sim);
                prev = v;
                mask &= ~(1u << (k[p] & 0xFu));
            }
        }
        tile[il][lane] = sim;
    }
    __syncthreads();

    // coalesced writes: tile and (if off-diagonal) transpose
#pragma unroll
    for (int q = 0; q < 2; q++) {
        const int il = w + 16 * q;
        g_sims[(I * 32 + il) * NROWS + J * 32 + lane] = tile[il][lane];
    }
    if (I != J) {
#pragma unroll
        for (int q = 0; q < 2; q++) {
            const int il = w + 16 * q;
            g_sims[(J * 32 + il) * NROWS + I * 32 + lane] = tile[lane][il];
        }
    }
}

// ---------------------------------------------------------------------------
// Kernel 4: per-row top-32 + softmax vote. 1024 blocks x 1024 threads, 2/SM.
// ---------------------------------------------------------------------------
__global__ void __launch_bounds__(1024, 2)
topk_kernel(const int* __restrict__ y, float* __restrict__ out)
{
    __shared__ float sA[NROWS];  __shared__ int iA[NROWS];
    __shared__ float sB[512];    __shared__ int iB[512];

    const int i    = blockIdx.x;
    const int tid  = threadIdx.x;
    const int lane = tid & 31, w = tid >> 5;

    float val = g_sims[i * NROWS + tid];
    int   idx = tid;

    // per-warp bitonic sort (descending)
#pragma unroll
    for (int kk = 2; kk <= 32; kk <<= 1) {
#pragma unroll
        for (int jj = kk >> 1; jj > 0; jj >>= 1) {
            float ov = __shfl_xor_sync(0xffffffffu, val, jj);
            int   oi = __shfl_xor_sync(0xffffffffu, idx, jj);
            bool lower   = (lane & jj) == 0;
            bool dirdesc = (lane & kk) == 0;
            bool takeMax = dirdesc ? lower : !lower;
            bool sw = takeMax ? (ov > val) : (ov < val);
            if (sw) { val = ov; idx = oi; }
        }
    }
    sA[w*32 + lane] = val;
    iA[w*32 + lane] = idx;
    __syncthreads();

    // merge tree: 32 sorted lists -> 1 (top-32 kept per merge)
#define MERGE_STAGE(NACT, SRCV, SRCI, DSTV, DSTI)                             \
    if (w < (NACT)) {                                                         \
        float av = SRCV[(2*w)*32 + lane];                                     \
        int   ai = SRCI[(2*w)*32 + lane];                                     \
        float bv = SRCV[(2*w+1)*32 + (31 - lane)];                            \
        int   bi = SRCI[(2*w+1)*32 + (31 - lane)];                            \
        float mv; int mi;                                                     \
        if (av >= bv) { mv = av; mi = ai; } else { mv = bv; mi = bi; }        \
        _Pragma("unroll")                                                     \
        for (int off = 16; off; off >>= 1) {                                  \
            float ov2 = __shfl_xor_sync(0xffffffffu, mv, off);                \
            int   oi2 = __shfl_xor_sync(0xffffffffu, mi, off);                \
            bool up = (lane & off) == 0;                                      \
            bool take = up ? (ov2 > mv) : (ov2 < mv);                         \
            if (take) { mv = ov2; mi = oi2; }                                 \
        }                                                                     \
        DSTV[w*32 + lane] = mv; DSTI[w*32 + lane] = mi;                       \
    }                                                                         \
    __syncthreads();

    MERGE_STAGE(16, sA, iA, sB, iB)
    MERGE_STAGE(8,  sB, iB, sA, iA)
    MERGE_STAGE(4,  sA, iA, sB, iB)
    MERGE_STAGE(2,  sB, iB, sA, iA)
#undef MERGE_STAGE

    if (w == 0) {
        float av = sA[lane];
        int   ai = iA[lane];
        float bv = sA[32 + (31 - lane)];
        int   bi = iA[32 + (31 - lane)];
        float mv; int mi;
        if (av >= bv) { mv = av; mi = ai; } else { mv = bv; mi = bi; }
#pragma unroll
        for (int off = 16; off; off >>= 1) {
            float ov2 = __shfl_xor_sync(0xffffffffu, mv, off);
            int   oi2 = __shfl_xor_sync(0xffffffffu, mi, off);
            bool up = (lane & off) == 0;
            bool take = up ? (ov2 > mv) : (ov2 < mv);
            if (take) { mv = ov2; mi = oi2; }
        }
        float vmax = __shfl_sync(0xffffffffu, mv, 0);
        float e = __expf((mv - vmax) * 2.0f);   // 1/TEMP = 2
        float s = e;
#pragma unroll
        for (int off = 16; off; off >>= 1) s += __shfl_xor_sync(0xffffffffu, s, off);
        float wgt = e / s;
        int label = y[mi];
#pragma unroll
        for (int c = 0; c < NCLS; c++) {
            float vc = (label == c) ? wgt : 0.0f;
#pragma unroll
            for (int off = 16; off; off >>= 1) vc += __shfl_xor_sync(0xffffffffu, vc, off);
            if (lane == 0) out[i*NCLS + c] = vc;
        }
    }
}

// ---------------------------------------------------------------------------
extern "C" void kernel_launch(void* const* d_in, const int* in_sizes, int n_in,
                              void* d_out, int out_size)
{
    const float* X    = (const float*)d_in[0];
    const int*   y    = (const int*)  d_in[1];
    const float* w1   = (const float*)d_in[2];
    const float* b1   = (const float*)d_in[3];
    const float* w2   = (const float*)d_in[4];
    const float* b2   = (const float*)d_in[5];
    const float* lng  = (const float*)d_in[6];
    const float* lnb  = (const float*)d_in[7];
    const float* w3   = (const float*)d_in[8];
    const float* b3   = (const float*)d_in[9];
    const float* cw1  = (const float*)d_in[10];
    const float* cb1  = (const float*)d_in[11];
    const float* cw2  = (const float*)d_in[12];
    const float* cb2  = (const float*)d_in[13];
    float* out = (float*)d_out;

    enc_kernel<<<32, 32>>>(X, w1, b1, w2, b2, lng, lnb, w3, b3);
    capgen_kernel<<<1, 1024>>>(cw1, cb1, cw2, cb2, out);
    sym_kernel<<<528, 512>>>(X);
    topk_kernel<<<1024, 1024>>>(y, out);
}

// round 6
// speedup vs baseline: 1.0969x; 1.0969x over previous
#include <cuda_runtime.h>
#include <cstdint>

#define NROWS 1024
#define DF    12
#define NMASK 4096          // 2^D
#define KSEL  32
#define NCLS  10

// Scratch (no cudaMalloc allowed)
__device__ float g_cap_lookup[NMASK];     // cap_lookup[mask], [0]=0
__device__ float g_partial[32][16];       // per-block h3 partial sums
__device__ float g_sims[NROWS * NROWS];   // full similarity matrix (4MB)
__device__ float g_cv[NROWS * 128];       // per-row 4x32 sorted candidates (vals)
__device__ int   g_ci[NROWS * 128];       // per-row 4x32 sorted candidates (idx)

// ---------------------------------------------------------------------------
// Kernel 1: encoder MLP. 32 blocks x 32 threads, 1 row/thread.
// ---------------------------------------------------------------------------
__global__ void __launch_bounds__(32, 1)
enc_kernel(const float* __restrict__ X,
           const float* __restrict__ w1, const float* __restrict__ b1,
           const float* __restrict__ w2, const float* __restrict__ b2,
           const float* __restrict__ lng, const float* __restrict__ lnb,
           const float* __restrict__ w3, const float* __restrict__ b3)
{
    const int lane = threadIdx.x;
    const int row  = blockIdx.x * 32 + lane;

    const float4* xr = (const float4*)(X + row * DF);
    float4 x0 = xr[0], x1 = xr[1], x2 = xr[2];

    float h1[32];
#pragma unroll
    for (int o = 0; o < 32; o++) {
        const float4* wr = (const float4*)(w1 + o * DF);
        float4 a0 = wr[0], a1 = wr[1], a2 = wr[2];
        float a = b1[o];
        a = fmaf(x0.x, a0.x, a); a = fmaf(x0.y, a0.y, a);
        a = fmaf(x0.z, a0.z, a); a = fmaf(x0.w, a0.w, a);
        a = fmaf(x1.x, a1.x, a); a = fmaf(x1.y, a1.y, a);
        a = fmaf(x1.z, a1.z, a); a = fmaf(x1.w, a1.w, a);
        a = fmaf(x2.x, a2.x, a); a = fmaf(x2.y, a2.y, a);
        a = fmaf(x2.z, a2.z, a); a = fmaf(x2.w, a2.w, a);
        h1[o] = fmaxf(a, 0.0f);
    }

    float h2[16];
#pragma unroll
    for (int o = 0; o < 16; o++) {
        const float4* wr = (const float4*)(w2 + o * 32);
        float a = b2[o];
#pragma unroll
        for (int q = 0; q < 8; q++) {
            float4 v = wr[q];
            a = fmaf(h1[q*4+0], v.x, a);
            a = fmaf(h1[q*4+1], v.y, a);
            a = fmaf(h1[q*4+2], v.z, a);
            a = fmaf(h1[q*4+3], v.w, a);
        }
        h2[o] = fmaxf(a, 0.0f);
    }

    float mu = 0.0f;
#pragma unroll
    for (int o = 0; o < 16; o++) mu += h2[o];
    mu *= (1.0f/16.0f);
    float var = 0.0f;
#pragma unroll
    for (int o = 0; o < 16; o++) { float dd = h2[o] - mu; var = fmaf(dd, dd, var); }
    var *= (1.0f/16.0f);
    float rs = rsqrtf(var + 1e-5f);
    float hn[16];
#pragma unroll
    for (int o = 0; o < 16; o++) hn[o] = fmaf((h2[o]-mu)*rs, lng[o], lnb[o]);

#pragma unroll
    for (int o = 0; o < 16; o++) {
        const float4* wr = (const float4*)(w3 + o * 16);
        float a = b3[o];
#pragma unroll
        for (int q = 0; q < 4; q++) {
            float4 v = wr[q];
            a = fmaf(hn[q*4+0], v.x, a);
            a = fmaf(hn[q*4+1], v.y, a);
            a = fmaf(hn[q*4+2], v.z, a);
            a = fmaf(hn[q*4+3], v.w, a);
        }
#pragma unroll
        for (int off = 16; off; off >>= 1) a += __shfl_xor_sync(0xffffffffu, a, off);
        if (lane == 0) g_partial[blockIdx.x][o] = a;
    }
}

// ---------------------------------------------------------------------------
// Kernel 2: capacity increments, 32 blocks x 128 threads (1 mask/thread).
// ---------------------------------------------------------------------------
__global__ void incr_kernel(const float* __restrict__ cw1, const float* __restrict__ cb1,
                            const float* __restrict__ cw2, const float* __restrict__ cb2)
{
    __shared__ float lat[16], hc[16];
    int tid = threadIdx.x;

    if (tid < 16) {
        float s = 0.0f;
#pragma unroll
        for (int b = 0; b < 32; b++) s += g_partial[b][tid];
        lat[tid] = s * (1.0f/1024.0f);
    }
    __syncthreads();
    if (tid < 16) {
        float a = cb1[tid];
#pragma unroll
        for (int f = 0; f < 16; f++) a = fmaf(lat[f], cw1[tid*16 + f], a);
        hc[tid] = fmaxf(a, 0.0f);
    }
    __syncthreads();

    int m = blockIdx.x * 128 + tid;
    // reuse g_cv's tail? no -- write increments into g_cap_lookup staging via g_sims? keep simple:
    if (m == 0) { ((float*)g_cv)[0] = 0.0f; return; }   // stage increments in g_cv (overwritten later)
    int r = m - 1;
    const float4* wr = (const float4*)(cw2 + r*16);
    float4 a0 = wr[0], a1 = wr[1], a2 = wr[2], a3 = wr[3];
    float z = cb2[r];
    z = fmaf(a0.x, hc[0],  z); z = fmaf(a0.y, hc[1],  z);
    z = fmaf(a0.z, hc[2],  z); z = fmaf(a0.w, hc[3],  z);
    z = fmaf(a1.x, hc[4],  z); z = fmaf(a1.y, hc[5],  z);
    z = fmaf(a1.z, hc[6],  z); z = fmaf(a1.w, hc[7],  z);
    z = fmaf(a2.x, hc[8],  z); z = fmaf(a2.y, hc[9],  z);
    z = fmaf(a2.z, hc[10], z); z = fmaf(a2.w, hc[11], z);
    z = fmaf(a3.x, hc[12], z); z = fmaf(a3.y, hc[13], z);
    z = fmaf(a3.z, hc[14], z); z = fmaf(a3.w, hc[15], z);
    ((float*)g_cv)[m] = 0.1f / (1.0f + __expf(-z));
}

// ---------------------------------------------------------------------------
// Kernel 3: zeta (subset-sum) transform, normalize, write cap_lookup + caps out
// ---------------------------------------------------------------------------
__global__ void zeta_kernel(float* __restrict__ out)
{
    __shared__ float g[NMASK];
    int tid = threadIdx.x;
    for (int m = tid; m < NMASK; m += 1024) g[m] = ((const float*)g_cv)[m];
    __syncthreads();

#pragma unroll
    for (int bit = 0; bit < DF; bit++) {
#pragma unroll
        for (int t = 0; t < 2; t++) {
            int i = t * 1024 + tid;
            int low = i & ((1 << bit) - 1);
            int m = ((i >> bit) << (bit + 1)) | (1 << bit) | low;
            g[m] += g[m ^ (1 << bit)];
        }
        __syncthreads();
    }

    float nrm = g[NMASK-1] + 1e-8f;
    for (int m = tid; m < NMASK; m += 1024) {
        float c = g[m] / nrm;
        g_cap_lookup[m] = c;
        if (m >= 1) out[NROWS*NCLS + m - 1] = c;   // caps output (S=4095)
    }
}

// ---------------------------------------------------------------------------
// Kernel 4: symmetric Choquet half-tiles. 1056 blocks (528 tiles x 2 halves)
// x 256 threads, 2 pairs/thread. Padded smem staging, coalesced dual writes.
// ---------------------------------------------------------------------------
__global__ void __launch_bounds__(256)
sym_kernel(const float* __restrict__ X)
{
    __shared__ float caps[NMASK];
    __shared__ float xiT[DF][17];    // 16 I-rows of this half
    __shared__ float xjT[DF][33];    // 32 J-rows
    __shared__ float tile[16][33];

    const int tid  = threadIdx.x;
    const int lane = tid & 31, w = tid >> 5;   // w in [0,8)

    // decode: tile t (upper-tri I>=J) and half h
    int t = blockIdx.x >> 1;
    int h = blockIdx.x & 1;
    int I = (int)((sqrtf(8.0f * (float)t + 1.0f) - 1.0f) * 0.5f);
    if (I * (I + 1) / 2 > t) I--;
    if ((I + 1) * (I + 2) / 2 <= t) I++;
    int J = t - I * (I + 1) / 2;

    // caps -> smem (4096 floats, 4 float4 per thread)
    {
        const float4* src = (const float4*)g_cap_lookup;
        float4* dst = (float4*)caps;
#pragma unroll
        for (int r = 0; r < 4; r++) dst[tid + 256*r] = src[tid + 256*r];
    }
    // X rows, transposed into smem
    if (tid < 192) {
        int r = tid / DF, d = tid - r * DF;
        xiT[d][r] = X[(I * 32 + h * 16 + r) * DF + d];
    }
    for (int u = tid; u < 384; u += 256) {
        int r = u / DF, d = u - r * DF;
        xjT[d][r] = X[(J * 32 + r) * DF + d];
    }
    __syncthreads();

    const int j = J * 32 + lane;
    float pj[DF];
#pragma unroll
    for (int d = 0; d < DF; d++) pj[d] = xjT[d][lane];

#pragma unroll
    for (int q = 0; q < 2; q++) {
        const int il = w + 8 * q;            // local row 0..15
        const int i  = I * 32 + h * 16 + il;
        float sim;
        if (i == j) {
            sim = -1e9f;                     // exclude self
        } else {
            unsigned k[DF];
#pragma unroll
            for (int d = 0; d < DF; d++) {
                float diff = pj[d] - xiT[d][il];
                k[d] = (__float_as_uint(diff) & 0x7FFFFFF0u) | (unsigned)d;
            }
            // Batcher odd-even mergesort (descending), n=12
#pragma unroll
            for (int p = 1; p < DF; p <<= 1) {
#pragma unroll
                for (int kk = p; kk >= 1; kk >>= 1) {
#pragma unroll
                    for (int jj = kk % p; jj <= DF - 1 - kk; jj += 2 * kk) {
#pragma unroll
                        for (int ii = 0; ii < kk; ii++) {
                            int a = ii + jj, c = ii + jj + kk;
                            if (c < DF && (a / (2 * p)) == (c / (2 * p))) {
                                unsigned lo = umin(k[a], k[c]);
                                unsigned hi = umax(k[a], k[c]);
                                k[a] = hi; k[c] = lo;
                            }
                        }
                    }
                }
            }
            // Choquet integral
            float prev = 0.0f; sim = 0.0f;
            unsigned mask = (unsigned)(NMASK - 1);
#pragma unroll
            for (int p = 0; p < DF; p++) {
                float dpos = __uint_as_float(k[p] & 0xFFFFFFF0u);
                float v = __expf(-dpos);
                sim = fmaf(v - prev, caps[mask], sim);
                prev = v;
                mask &= ~(1u << (k[p] & 0xFu));
            }
        }
        tile[il][lane] = sim;
    }
    __syncthreads();

    // normal write: 16 rows x 32 cols coalesced
#pragma unroll
    for (int q = 0; q < 2; q++) {
        const int il = w + 8 * q;
        g_sims[(I * 32 + h * 16 + il) * NROWS + J * 32 + lane] = tile[il][lane];
    }
    // transpose write (off-diagonal tiles): 32 rows x 16 cols, 64B runs
    if (I != J) {
        for (int u = tid; u < 512; u += 256) {
            int row2 = u >> 4, c = u & 15;
            g_sims[(J * 32 + row2) * NROWS + I * 32 + h * 16 + c] = tile[c][row2];
        }
    }
}

// shared merge macro: merge sorted-descending 32-lists pairwise, keep top-32
#define MERGE_STAGE(NACT, SRCV, SRCI, DSTV, DSTI)                             \
    if (w < (NACT)) {                                                         \
        float av = SRCV[(2*w)*32 + lane];                                     \
        int   ai = SRCI[(2*w)*32 + lane];                                     \
        float bv = SRCV[(2*w+1)*32 + (31 - lane)];                            \
        int   bi = SRCI[(2*w+1)*32 + (31 - lane)];                            \
        float mv; int mi;                                                     \
        if (av >= bv) { mv = av; mi = ai; } else { mv = bv; mi = bi; }        \
        _Pragma("unroll")                                                     \
        for (int off = 16; off; off >>= 1) {                                  \
            float ov2 = __shfl_xor_sync(0xffffffffu, mv, off);                \
            int   oi2 = __shfl_xor_sync(0xffffffffu, mi, off);                \
            bool up = (lane & off) == 0;                                      \
            bool take = up ? (ov2 > mv) : (ov2 < mv);                         \
            if (take) { mv = ov2; mi = oi2; }                                 \
        }                                                                     \
        DSTV[w*32 + lane] = mv; DSTI[w*32 + lane] = mi;                       \
    }                                                                         \
    __syncthreads();

// ---------------------------------------------------------------------------
// Kernel 5a: chunk top-32. 4096 blocks (row r, chunk c) x 256 threads.
// Produces sorted top-32 of each 256-element chunk.
// ---------------------------------------------------------------------------
__global__ void __launch_bounds__(256)
topk_part_kernel(float* __restrict__ dummy)
{
    __shared__ float sA[256];  __shared__ int iA[256];
    __shared__ float sB[128];  __shared__ int iB[128];

    const int r   = blockIdx.x >> 2;
    const int c   = blockIdx.x & 3;
    const int tid = threadIdx.x;
    const int lane = tid & 31, w = tid >> 5;

    const int j = c * 256 + tid;
    float val = (j == r) ? -1e9f : g_sims[r * NROWS + j];
    int   idx = j;

    // per-warp bitonic sort (descending)
#pragma unroll
    for (int kk = 2; kk <= 32; kk <<= 1) {
#pragma unroll
        for (int jj = kk >> 1; jj > 0; jj >>= 1) {
            float ov = __shfl_xor_sync(0xffffffffu, val, jj);
            int   oi = __shfl_xor_sync(0xffffffffu, idx, jj);
            bool lower   = (lane & jj) == 0;
            bool dirdesc = (lane & kk) == 0;
            bool takeMax = dirdesc ? lower : !lower;
            bool sw = takeMax ? (ov > val) : (ov < val);
            if (sw) { val = ov; idx = oi; }
        }
    }
    sA[w*32 + lane] = val;
    iA[w*32 + lane] = idx;
    __syncthreads();

    MERGE_STAGE(4, sA, iA, sB, iB)   // 8 -> 4
    MERGE_STAGE(2, sB, iB, sA, iA)   // 4 -> 2

    // final merge (2 -> 1) in warp 0, write candidates
    if (w == 0) {
        float av = sA[lane];
        int   ai = iA[lane];
        float bv = sA[32 + (31 - lane)];
        int   bi = iA[32 + (31 - lane)];
        float mv; int mi;
        if (av >= bv) { mv = av; mi = ai; } else { mv = bv; mi = bi; }
#pragma unroll
        for (int off = 16; off; off >>= 1) {
            float ov2 = __shfl_xor_sync(0xffffffffu, mv, off);
            int   oi2 = __shfl_xor_sync(0xffffffffu, mi, off);
            bool up = (lane & off) == 0;
            bool take = up ? (ov2 > mv) : (ov2 < mv);
            if (take) { mv = ov2; mi = oi2; }
        }
        g_cv[r * 128 + c * 32 + lane] = mv;
        g_ci[r * 128 + c * 32 + lane] = mi;
    }
}

// ---------------------------------------------------------------------------
// Kernel 5b: merge 4 sorted candidate lists -> top-32 -> softmax vote.
// 1024 blocks x 128 threads.
// ---------------------------------------------------------------------------
__global__ void __launch_bounds__(128)
vote_kernel(const int* __restrict__ y, float* __restrict__ out)
{
    __shared__ float sA[128];  __shared__ int iA[128];
    __shared__ float sB[64];   __shared__ int iB[64];

    const int r    = blockIdx.x;
    const int tid  = threadIdx.x;
    const int lane = tid & 31, w = tid >> 5;

    sA[tid] = g_cv[r * 128 + tid];   // 4 sorted-descending 32-lists
    iA[tid] = g_ci[r * 128 + tid];
    __syncthreads();

    MERGE_STAGE(2, sA, iA, sB, iB)   // 4 -> 2

    if (w == 0) {
        float av = sB[lane];
        int   ai = iB[lane];
        float bv = sB[32 + (31 - lane)];
        int   bi = iB[32 + (31 - lane)];
        float mv; int mi;
        if (av >= bv) { mv = av; mi = ai; } else { mv = bv; mi = bi; }
#pragma unroll
        for (int off = 16; off; off >>= 1) {
            float ov2 = __shfl_xor_sync(0xffffffffu, mv, off);
            int   oi2 = __shfl_xor_sync(0xffffffffu, mi, off);
            bool up = (lane & off) == 0;
            bool take = up ? (ov2 > mv) : (ov2 < mv);
            if (take) { mv = ov2; mi = oi2; }
        }
        float vmax = __shfl_sync(0xffffffffu, mv, 0);
        float e = __expf((mv - vmax) * 2.0f);   // 1/TEMP = 2
        float s = e;
#pragma unroll
        for (int off = 16; off; off >>= 1) s += __shfl_xor_sync(0xffffffffu, s, off);
        float wgt = e / s;
        int label = y[mi];
#pragma unroll
        for (int cc = 0; cc < NCLS; cc++) {
            float vc = (label == cc) ? wgt : 0.0f;
#pragma unroll
            for (int off = 16; off; off >>= 1) vc += __shfl_xor_sync(0xffffffffu, vc, off);
            if (lane == 0) out[r*NCLS + cc] = vc;
        }
    }
}

// ---------------------------------------------------------------------------
extern "C" void kernel_launch(void* const* d_in, const int* in_sizes, int n_in,
                              void* d_out, int out_size)
{
    const float* X    = (const float*)d_in[0];
    const int*   y    = (const int*)  d_in[1];
    const float* w1   = (const float*)d_in[2];
    const float* b1   = (const float*)d_in[3];
    const float* w2   = (const float*)d_in[4];
    const float* b2   = (const float*)d_in[5];
    const float* lng  = (const float*)d_in[6];
    const float* lnb  = (const float*)d_in[7];
    const float* w3   = (const float*)d_in[8];
    const float* b3   = (const float*)d_in[9];
    const float* cw1  = (const float*)d_in[10];
    const float* cb1  = (const float*)d_in[11];
    const float* cw2  = (const float*)d_in[12];
    const float* cb2  = (const float*)d_in[13];
    float* out = (float*)d_out;

    enc_kernel<<<32, 32>>>(X, w1, b1, w2, b2, lng, lnb, w3, b3);
    incr_kernel<<<32, 128>>>(cw1, cb1, cw2, cb2);
    zeta_kernel<<<1, 1024>>>(out);
    sym_kernel<<<1056, 256>>>(X);
    topk_part_kernel<<<4096, 256>>>(out);
    vote_kernel<<<1024, 128>>>(y, out);
}

// round 7
// speedup vs baseline: 1.1121x; 1.0139x over previous
#include <cuda_runtime.h>
#include <cstdint>

#define NROWS 1024
#define DF    12
#define NMASK 4096          // 2^D
#define KSEL  32
#define NCLS  10

// Scratch (no cudaMalloc allowed)
__device__ float g_cap_lookup[NMASK];     // cap_lookup[mask], [0]=0
__device__ float g_partial[32][16];       // per-block h3 partial sums
__device__ float g_sims[NROWS * NROWS];   // full similarity matrix (4MB)

// ---------------------------------------------------------------------------
// Kernel 1: encoder MLP. 32 blocks x 32 threads, 1 row/thread.
// ---------------------------------------------------------------------------
__global__ void __launch_bounds__(32, 1)
enc_kernel(const float* __restrict__ X,
           const float* __restrict__ w1, const float* __restrict__ b1,
           const float* __restrict__ w2, const float* __restrict__ b2,
           const float* __restrict__ lng, const float* __restrict__ lnb,
           const float* __restrict__ w3, const float* __restrict__ b3)
{
    const int lane = threadIdx.x;
    const int row  = blockIdx.x * 32 + lane;

    const float4* xr = (const float4*)(X + row * DF);
    float4 x0 = xr[0], x1 = xr[1], x2 = xr[2];

    float h1[32];
#pragma unroll
    for (int o = 0; o < 32; o++) {
        const float4* wr = (const float4*)(w1 + o * DF);
        float4 a0 = wr[0], a1 = wr[1], a2 = wr[2];
        float a = b1[o];
        a = fmaf(x0.x, a0.x, a); a = fmaf(x0.y, a0.y, a);
        a = fmaf(x0.z, a0.z, a); a = fmaf(x0.w, a0.w, a);
        a = fmaf(x1.x, a1.x, a); a = fmaf(x1.y, a1.y, a);
        a = fmaf(x1.z, a1.z, a); a = fmaf(x1.w, a1.w, a);
        a = fmaf(x2.x, a2.x, a); a = fmaf(x2.y, a2.y, a);
        a = fmaf(x2.z, a2.z, a); a = fmaf(x2.w, a2.w, a);
        h1[o] = fmaxf(a, 0.0f);
    }

    float h2[16];
#pragma unroll
    for (int o = 0; o < 16; o++) {
        const float4* wr = (const float4*)(w2 + o * 32);
        float a = b2[o];
#pragma unroll
        for (int q = 0; q < 8; q++) {
            float4 v = wr[q];
            a = fmaf(h1[q*4+0], v.x, a);
            a = fmaf(h1[q*4+1], v.y, a);
            a = fmaf(h1[q*4+2], v.z, a);
            a = fmaf(h1[q*4+3], v.w, a);
        }
        h2[o] = fmaxf(a, 0.0f);
    }

    float mu = 0.0f;
#pragma unroll
    for (int o = 0; o < 16; o++) mu += h2[o];
    mu *= (1.0f/16.0f);
    float var = 0.0f;
#pragma unroll
    for (int o = 0; o < 16; o++) { float dd = h2[o] - mu; var = fmaf(dd, dd, var); }
    var *= (1.0f/16.0f);
    float rs = rsqrtf(var + 1e-5f);
    float hn[16];
#pragma unroll
    for (int o = 0; o < 16; o++) hn[o] = fmaf((h2[o]-mu)*rs, lng[o], lnb[o]);

#pragma unroll
    for (int o = 0; o < 16; o++) {
        const float4* wr = (const float4*)(w3 + o * 16);
        float a = b3[o];
#pragma unroll
        for (int q = 0; q < 4; q++) {
            float4 v = wr[q];
            a = fmaf(hn[q*4+0], v.x, a);
            a = fmaf(hn[q*4+1], v.y, a);
            a = fmaf(hn[q*4+2], v.z, a);
            a = fmaf(hn[q*4+3], v.w, a);
        }
#pragma unroll
        for (int off = 16; off; off >>= 1) a += __shfl_xor_sync(0xffffffffu, a, off);
        if (lane == 0) g_partial[blockIdx.x][o] = a;
    }
}

// ---------------------------------------------------------------------------
// Kernel 2 (fused incr + zeta): latent -> hc -> increments -> subset-sum
// zeta transform -> normalized cap_lookup + caps output. 1 block x 1024 thr.
// ---------------------------------------------------------------------------
__global__ void __launch_bounds__(1024, 1)
capgen_kernel(const float* __restrict__ cw1, const float* __restrict__ cb1,
              const float* __restrict__ cw2, const float* __restrict__ cb2,
              float* __restrict__ out)
{
    __shared__ float g[NMASK];
    __shared__ float lat[16], hc[16];
    const int tid = threadIdx.x;

    if (tid < 16) {
        float s = 0.0f;
#pragma unroll
        for (int b = 0; b < 32; b++) s += g_partial[b][tid];
        lat[tid] = s * (1.0f/1024.0f);
    }
    __syncthreads();
    if (tid < 16) {
        float a = cb1[tid];
#pragma unroll
        for (int f = 0; f < 16; f++) a = fmaf(lat[f], cw1[tid*16 + f], a);
        hc[tid] = fmaxf(a, 0.0f);
    }
    __syncthreads();

    // increments: 4 masks per thread (coalesced 256KB cw2 read)
#pragma unroll
    for (int t = 0; t < 4; t++) {
        int m = t * 1024 + tid;
        if (m >= 1) {
            int r = m - 1;
            const float4* wr = (const float4*)(cw2 + r*16);
            float4 a0 = wr[0], a1 = wr[1], a2 = wr[2], a3 = wr[3];
            float z = cb2[r];
            z = fmaf(a0.x, hc[0],  z); z = fmaf(a0.y, hc[1],  z);
            z = fmaf(a0.z, hc[2],  z); z = fmaf(a0.w, hc[3],  z);
            z = fmaf(a1.x, hc[4],  z); z = fmaf(a1.y, hc[5],  z);
            z = fmaf(a1.z, hc[6],  z); z = fmaf(a1.w, hc[7],  z);
            z = fmaf(a2.x, hc[8],  z); z = fmaf(a2.y, hc[9],  z);
            z = fmaf(a2.z, hc[10], z); z = fmaf(a2.w, hc[11], z);
            z = fmaf(a3.x, hc[12], z); z = fmaf(a3.y, hc[13], z);
            z = fmaf(a3.z, hc[14], z); z = fmaf(a3.w, hc[15], z);
            g[m] = 0.1f / (1.0f + __expf(-z));
        } else {
            g[0] = 0.0f;
        }
    }
    __syncthreads();

    // subset-sum (zeta) transform: g[m] = sum_{b subset m} inc[b]
#pragma unroll
    for (int bit = 0; bit < DF; bit++) {
#pragma unroll
        for (int t = 0; t < 2; t++) {
            int i = t * 1024 + tid;
            int low = i & ((1 << bit) - 1);
            int m = ((i >> bit) << (bit + 1)) | (1 << bit) | low;
            g[m] += g[m ^ (1 << bit)];
        }
        __syncthreads();
    }

    float nrm = g[NMASK-1] + 1e-8f;
#pragma unroll
    for (int t = 0; t < 4; t++) {
        int m = t * 1024 + tid;
        float c = g[m] / nrm;
        g_cap_lookup[m] = c;
        if (m >= 1) out[NROWS*NCLS + m - 1] = c;   // caps output (S=4095)
    }
}

// ---------------------------------------------------------------------------
// Kernel 3: symmetric Choquet half-tiles. 1056 blocks (528 tiles x 2 halves)
// x 256 threads, 2 pairs/thread. Keys = exp-value floats with id packed into
// low 4 mantissa bits -> sort on FMA pipe (FMNMX), no MUFU in Choquet chain.
// ---------------------------------------------------------------------------
__global__ void __launch_bounds__(256)
sym_kernel(const float* __restrict__ X)
{
    __shared__ float caps[NMASK];
    __shared__ float xiT[DF][17];    // 16 I-rows of this half
    __shared__ float xjT[DF][33];    // 32 J-rows
    __shared__ float tile[16][33];

    const int tid  = threadIdx.x;
    const int lane = tid & 31, w = tid >> 5;   // w in [0,8)

    // decode: tile t (upper-tri I>=J) and half h
    int t = blockIdx.x >> 1;
    int h = blockIdx.x & 1;
    int I = (int)((sqrtf(8.0f * (float)t + 1.0f) - 1.0f) * 0.5f);
    if (I * (I + 1) / 2 > t) I--;
    if ((I + 1) * (I + 2) / 2 <= t) I++;
    int J = t - I * (I + 1) / 2;

    // caps -> smem (4096 floats, 4 float4 per thread)
    {
        const float4* src = (const float4*)g_cap_lookup;
        float4* dst = (float4*)caps;
#pragma unroll
        for (int r = 0; r < 4; r++) dst[tid + 256*r] = src[tid + 256*r];
    }
    // X rows, transposed into smem
    if (tid < 192) {
        int r = tid / DF, d = tid - r * DF;
        xiT[d][r] = X[(I * 32 + h * 16 + r) * DF + d];
    }
    for (int u = tid; u < 384; u += 256) {
        int r = u / DF, d = u - r * DF;
        xjT[d][r] = X[(J * 32 + r) * DF + d];
    }
    __syncthreads();

    const int j = J * 32 + lane;
    float pj[DF];
#pragma unroll
    for (int d = 0; d < DF; d++) pj[d] = xjT[d][lane];

#pragma unroll
    for (int q = 0; q < 2; q++) {
        const int il = w + 8 * q;            // local row 0..15
        const int i  = I * 32 + h * 16 + il;
        float sim;
        if (i == j) {
            sim = -1e9f;                     // exclude self
        } else {
            // keys: v = exp(-|diff|) in (0,1], id packed into low 4 mantissa
            // bits. Positive-float compare == uint compare, so sorting the
            // float keys ascending == vals ascending (== |diff| descending).
            float k[DF];
#pragma unroll
            for (int d = 0; d < DF; d++) {
                float diff = pj[d] - xiT[d][il];
                float v = exp2f(-1.442695041f * fabsf(diff));   // MUFU up-front
                k[d] = __uint_as_float((__float_as_uint(v) & 0xFFFFFFF0u)
                                       | (unsigned)d);
            }
            // Batcher odd-even mergesort (ascending), n=12, FMNMX comparators
#pragma unroll
            for (int p = 1; p < DF; p <<= 1) {
#pragma unroll
                for (int kk = p; kk >= 1; kk >>= 1) {
#pragma unroll
                    for (int jj = kk % p; jj <= DF - 1 - kk; jj += 2 * kk) {
#pragma unroll
                        for (int ii = 0; ii < kk; ii++) {
                            int a = ii + jj, c = ii + jj + kk;
                            if (c < DF && (a / (2 * p)) == (c / (2 * p))) {
                                float lo = fminf(k[a], k[c]);
                                float hi = fmaxf(k[a], k[c]);
                                k[a] = lo; k[c] = hi;
                            }
                        }
                    }
                }
            }
            // Choquet: sum_p (v_p - v_{p-1}) * cap[suffix_mask_p]; v from key
            float prev = 0.0f; sim = 0.0f;
            unsigned mask = (unsigned)(NMASK - 1);
#pragma unroll
            for (int p = 0; p < DF; p++) {
                unsigned kb = __float_as_uint(k[p]);
                float v = __uint_as_float(kb & 0xFFFFFFF0u);
                sim = fmaf(v - prev, caps[mask], sim);
                prev = v;
                mask &= ~(1u << (kb & 0xFu));
            }
        }
        tile[il][lane] = sim;
    }
    __syncthreads();

    // normal write: 16 rows x 32 cols coalesced
#pragma unroll
    for (int q = 0; q < 2; q++) {
        const int il = w + 8 * q;
        g_sims[(I * 32 + h * 16 + il) * NROWS + J * 32 + lane] = tile[il][lane];
    }
    // transpose write (off-diagonal tiles): 32 rows x 16 cols, 64B runs
    if (I != J) {
        for (int u = tid; u < 512; u += 256) {
            int row2 = u >> 4, c = u & 15;
            g_sims[(J * 32 + row2) * NROWS + I * 32 + h * 16 + c] = tile[c][row2];
        }
    }
}

// ---------------------------------------------------------------------------
// warp helpers for top-k
// ---------------------------------------------------------------------------
__device__ __forceinline__ void warp_sort32_desc(float& val, int& idx, int lane)
{
#pragma unroll
    for (int kk = 2; kk <= 32; kk <<= 1) {
#pragma unroll
        for (int jj = kk >> 1; jj > 0; jj >>= 1) {
            float ov = __shfl_xor_sync(0xffffffffu, val, jj);
            int   oi = __shfl_xor_sync(0xffffffffu, idx, jj);
            bool lower   = (lane & jj) == 0;
            bool dirdesc = (lane & kk) == 0;
            bool takeMax = dirdesc ? lower : !lower;
            bool sw = takeMax ? (ov > val) : (ov < val);
            if (sw) { val = ov; idx = oi; }
        }
    }
}

// merge two sorted-descending 32-lists (A in mv/mi, B in bv/bi), keep top-32
__device__ __forceinline__ void warp_merge32_desc(float& mv, int& mi,
                                                  float bv, int bi, int lane)
{
    float rv = __shfl_sync(0xffffffffu, bv, 31 - lane);
    int   ri = __shfl_sync(0xffffffffu, bi, 31 - lane);
    if (rv > mv) { mv = rv; mi = ri; }      // C[k] = max(A[k], B[31-k])
#pragma unroll
    for (int off = 16; off; off >>= 1) {    // bitonic clean, descending
        float ov = __shfl_xor_sync(0xffffffffu, mv, off);
        int   oi = __shfl_xor_sync(0xffffffffu, mi, off);
        bool up = (lane & off) == 0;
        bool take = up ? (ov > mv) : (ov < mv);
        if (take) { mv = ov; mi = oi; }
    }
}

// ---------------------------------------------------------------------------
// Kernel 4 (fused top-32 + vote). 1024 blocks (one row) x 256 threads.
// Each warp reduces its 128 elements to a register top-32, then 3 smem
// merge levels + softmax vote.
// ---------------------------------------------------------------------------
__global__ void __launch_bounds__(256)
topk_kernel(const int* __restrict__ y, float* __restrict__ out)
{
    __shared__ float sA[256];  __shared__ int iA[256];
    __shared__ float sB[128];  __shared__ int iB[128];

    const int r    = blockIdx.x;
    const int tid  = threadIdx.x;
    const int lane = tid & 31, w = tid >> 5;   // 8 warps

    // segment 0
    int j = w * 128 + lane;
    float mv = (j == r) ? -1e9f : g_sims[r * NROWS + j];
    int   mi = j;
    warp_sort32_desc(mv, mi, lane);

    // segments 1..3: sort then merge into running top-32
#pragma unroll
    for (int s = 1; s < 4; s++) {
        j = w * 128 + s * 32 + lane;
        float bv = (j == r) ? -1e9f : g_sims[r * NROWS + j];
        int   bi = j;
        warp_sort32_desc(bv, bi, lane);
        warp_merge32_desc(mv, mi, bv, bi, lane);
    }

    sA[w*32 + lane] = mv;
    iA[w*32 + lane] = mi;
    __syncthreads();

#define MERGE_STAGE(NACT, SRCV, SRCI, DSTV, DSTI)                             \
    if (w < (NACT)) {                                                         \
        float av = SRCV[(2*w)*32 + lane];                                     \
        int   ai = SRCI[(2*w)*32 + lane];                                     \
        float bv = SRCV[(2*w+1)*32 + (31 - lane)];                            \
        int   bi = SRCI[(2*w+1)*32 + (31 - lane)];                            \
        float xv; int xi;                                                     \
        if (av >= bv) { xv = av; xi = ai; } else { xv = bv; xi = bi; }        \
        _Pragma("unroll")                                                     \
        for (int off = 16; off; off >>= 1) {                                  \
            float ov2 = __shfl_xor_sync(0xffffffffu, xv, off);                \
            int   oi2 = __shfl_xor_sync(0xffffffffu, xi, off);                \
            bool up = (lane & off) == 0;                                      \
            bool take = up ? (ov2 > xv) : (ov2 < xv);                         \
            if (take) { xv = ov2; xi = oi2; }                                 \
        }                                                                     \
        DSTV[w*32 + lane] = xv; DSTI[w*32 + lane] = xi;                       \
    }                                                                         \
    __syncthreads();

    MERGE_STAGE(4, sA, iA, sB, iB)   // 8 -> 4
    MERGE_STAGE(2, sB, iB, sA, iA)   // 4 -> 2
#undef MERGE_STAGE

    // final merge (2 -> 1) + softmax vote in warp 0
    if (w == 0) {
        float av = sA[lane];
        int   ai = iA[lane];
        float bv = sA[32 + (31 - lane)];
        int   bi = iA[32 + (31 - lane)];
        float xv; int xi;
        if (av >= bv) { xv = av; xi = ai; } else { xv = bv; xi = bi; }
#pragma unroll
        for (int off = 16; off; off >>= 1) {
            float ov2 = __shfl_xor_sync(0xffffffffu, xv, off);
            int   oi2 = __shfl_xor_sync(0xffffffffu, xi, off);
            bool up = (lane & off) == 0;
            bool take = up ? (ov2 > xv) : (ov2 < xv);
            if (take) { xv = ov2; xi = oi2; }
        }
        float vmax = __shfl_sync(0xffffffffu, xv, 0);
        float e = __expf((xv - vmax) * 2.0f);   // 1/TEMP = 2
        float s = e;
#pragma unroll
        for (int off = 16; off; off >>= 1) s += __shfl_xor_sync(0xffffffffu, s, off);
        float wgt = e / s;
        int label = y[xi];
#pragma unroll
        for (int cc = 0; cc < NCLS; cc++) {
            float vc = (label == cc) ? wgt : 0.0f;
#pragma unroll
            for (int off = 16; off; off >>= 1) vc += __shfl_xor_sync(0xffffffffu, vc, off);
            if (lane == 0) out[r*NCLS + cc] = vc;
        }
    }
}

// ---------------------------------------------------------------------------
extern "C" void kernel_launch(void* const* d_in, const int* in_sizes, int n_in,
                              void* d_out, int out_size)
{
    const float* X    = (const float*)d_in[0];
    const int*   y    = (const int*)  d_in[1];
    const float* w1   = (const float*)d_in[2];
    const float* b1   = (const float*)d_in[3];
    const float* w2   = (const float*)d_in[4];
    const float* b2   = (const float*)d_in[5];
    const float* lng  = (const float*)d_in[6];
    const float* lnb  = (const float*)d_in[7];
    const float* w3   = (const float*)d_in[8];
    const float* b3   = (const float*)d_in[9];
    const float* cw1  = (const float*)d_in[10];
    const float* cb1  = (const float*)d_in[11];
    const float* cw2  = (const float*)d_in[12];
    const float* cb2  = (const float*)d_in[13];
    float* out = (float*)d_out;

    enc_kernel<<<32, 32>>>(X, w1, b1, w2, b2, lng, lnb, w3, b3);
    capgen_kernel<<<1, 1024>>>(cw1, cb1, cw2, cb2, out);
    sym_kernel<<<1056, 256>>>(X);
    topk_kernel<<<1024, 256>>>(y, out);
}

// round 8
// speedup vs baseline: 1.2310x; 1.1069x over previous
#include <cuda_runtime.h>
#include <cstdint>

#define NROWS 1024
#define DF    12
#define NMASK 4096          // 2^D
#define KSEL  32
#define NCLS  10

// Scratch (no cudaMalloc allowed)
__device__ float g_cap_lookup[NMASK];     // cap_lookup[mask], [0]=0
__device__ float g_partial[32][16];       // per-block h3 partial sums
__device__ float g_sims[NROWS * NROWS];   // full similarity matrix (4MB)

// ---------------------------------------------------------------------------
// Kernel 1: encoder MLP. 32 blocks x 32 threads, 1 row/thread.
// ---------------------------------------------------------------------------
__global__ void __launch_bounds__(32, 1)
enc_kernel(const float* __restrict__ X,
           const float* __restrict__ w1, const float* __restrict__ b1,
           const float* __restrict__ w2, const float* __restrict__ b2,
           const float* __restrict__ lng, const float* __restrict__ lnb,
           const float* __restrict__ w3, const float* __restrict__ b3)
{
    const int lane = threadIdx.x;
    const int row  = blockIdx.x * 32 + lane;

    const float4* xr = (const float4*)(X + row * DF);
    float4 x0 = xr[0], x1 = xr[1], x2 = xr[2];

    float h1[32];
#pragma unroll
    for (int o = 0; o < 32; o++) {
        const float4* wr = (const float4*)(w1 + o * DF);
        float4 a0 = wr[0], a1 = wr[1], a2 = wr[2];
        float a = b1[o];
        a = fmaf(x0.x, a0.x, a); a = fmaf(x0.y, a0.y, a);
        a = fmaf(x0.z, a0.z, a); a = fmaf(x0.w, a0.w, a);
        a = fmaf(x1.x, a1.x, a); a = fmaf(x1.y, a1.y, a);
        a = fmaf(x1.z, a1.z, a); a = fmaf(x1.w, a1.w, a);
        a = fmaf(x2.x, a2.x, a); a = fmaf(x2.y, a2.y, a);
        a = fmaf(x2.z, a2.z, a); a = fmaf(x2.w, a2.w, a);
        h1[o] = fmaxf(a, 0.0f);
    }

    float h2[16];
#pragma unroll
    for (int o = 0; o < 16; o++) {
        const float4* wr = (const float4*)(w2 + o * 32);
        float a = b2[o];
#pragma unroll
        for (int q = 0; q < 8; q++) {
            float4 v = wr[q];
            a = fmaf(h1[q*4+0], v.x, a);
            a = fmaf(h1[q*4+1], v.y, a);
            a = fmaf(h1[q*4+2], v.z, a);
            a = fmaf(h1[q*4+3], v.w, a);
        }
        h2[o] = fmaxf(a, 0.0f);
    }

    float mu = 0.0f;
#pragma unroll
    for (int o = 0; o < 16; o++) mu += h2[o];
    mu *= (1.0f/16.0f);
    float var = 0.0f;
#pragma unroll
    for (int o = 0; o < 16; o++) { float dd = h2[o] - mu; var = fmaf(dd, dd, var); }
    var *= (1.0f/16.0f);
    float rs = rsqrtf(var + 1e-5f);
    float hn[16];
#pragma unroll
    for (int o = 0; o < 16; o++) hn[o] = fmaf((h2[o]-mu)*rs, lng[o], lnb[o]);

#pragma unroll
    for (int o = 0; o < 16; o++) {
        const float4* wr = (const float4*)(w3 + o * 16);
        float a = b3[o];
#pragma unroll
        for (int q = 0; q < 4; q++) {
            float4 v = wr[q];
            a = fmaf(hn[q*4+0], v.x, a);
            a = fmaf(hn[q*4+1], v.y, a);
            a = fmaf(hn[q*4+2], v.z, a);
            a = fmaf(hn[q*4+3], v.w, a);
        }
#pragma unroll
        for (int off = 16; off; off >>= 1) a += __shfl_xor_sync(0xffffffffu, a, off);
        if (lane == 0) g_partial[blockIdx.x][o] = a;
    }
}

// ---------------------------------------------------------------------------
// Kernel 2 (fused incr + zeta): latent -> hc -> increments -> subset-sum
// zeta transform -> normalized cap_lookup + caps output. 1 block x 1024 thr.
// ---------------------------------------------------------------------------
__global__ void __launch_bounds__(1024, 1)
capgen_kernel(const float* __restrict__ cw1, const float* __restrict__ cb1,
              const float* __restrict__ cw2, const float* __restrict__ cb2,
              float* __restrict__ out)
{
    __shared__ float g[NMASK];
    __shared__ float lat[16], hc[16];
    const int tid = threadIdx.x;

    if (tid < 16) {
        float s = 0.0f;
#pragma unroll
        for (int b = 0; b < 32; b++) s += g_partial[b][tid];
        lat[tid] = s * (1.0f/1024.0f);
    }
    __syncthreads();
    if (tid < 16) {
        float a = cb1[tid];
#pragma unroll
        for (int f = 0; f < 16; f++) a = fmaf(lat[f], cw1[tid*16 + f], a);
        hc[tid] = fmaxf(a, 0.0f);
    }
    __syncthreads();

#pragma unroll
    for (int t = 0; t < 4; t++) {
        int m = t * 1024 + tid;
        if (m >= 1) {
            int r = m - 1;
            const float4* wr = (const float4*)(cw2 + r*16);
            float4 a0 = wr[0], a1 = wr[1], a2 = wr[2], a3 = wr[3];
            float z = cb2[r];
            z = fmaf(a0.x, hc[0],  z); z = fmaf(a0.y, hc[1],  z);
            z = fmaf(a0.z, hc[2],  z); z = fmaf(a0.w, hc[3],  z);
            z = fmaf(a1.x, hc[4],  z); z = fmaf(a1.y, hc[5],  z);
            z = fmaf(a1.z, hc[6],  z); z = fmaf(a1.w, hc[7],  z);
            z = fmaf(a2.x, hc[8],  z); z = fmaf(a2.y, hc[9],  z);
            z = fmaf(a2.z, hc[10], z); z = fmaf(a2.w, hc[11], z);
            z = fmaf(a3.x, hc[12], z); z = fmaf(a3.y, hc[13], z);
            z = fmaf(a3.z, hc[14], z); z = fmaf(a3.w, hc[15], z);
            g[m] = 0.1f / (1.0f + __expf(-z));
        } else {
            g[0] = 0.0f;
        }
    }
    __syncthreads();

#pragma unroll
    for (int bit = 0; bit < DF; bit++) {
#pragma unroll
        for (int t = 0; t < 2; t++) {
            int i = t * 1024 + tid;
            int low = i & ((1 << bit) - 1);
            int m = ((i >> bit) << (bit + 1)) | (1 << bit) | low;
            g[m] += g[m ^ (1 << bit)];
        }
        __syncthreads();
    }

    float nrm = g[NMASK-1] + 1e-8f;
#pragma unroll
    for (int t = 0; t < 4; t++) {
        int m = t * 1024 + tid;
        float c = g[m] / nrm;
        g_cap_lookup[m] = c;
        if (m >= 1) out[NROWS*NCLS + m - 1] = c;   // caps output (S=4095)
    }
}

// ---------------------------------------------------------------------------
// Kernel 3: symmetric Choquet half-tiles. 1056 blocks x 256 threads.
// ---------------------------------------------------------------------------
__global__ void __launch_bounds__(256)
sym_kernel(const float* __restrict__ X)
{
    __shared__ float caps[NMASK];
    __shared__ float xiT[DF][17];
    __shared__ float xjT[DF][33];
    __shared__ float tile[16][33];

    const int tid  = threadIdx.x;
    const int lane = tid & 31, w = tid >> 5;

    int t = blockIdx.x >> 1;
    int h = blockIdx.x & 1;
    int I = (int)((sqrtf(8.0f * (float)t + 1.0f) - 1.0f) * 0.5f);
    if (I * (I + 1) / 2 > t) I--;
    if ((I + 1) * (I + 2) / 2 <= t) I++;
    int J = t - I * (I + 1) / 2;

    {
        const float4* src = (const float4*)g_cap_lookup;
        float4* dst = (float4*)caps;
#pragma unroll
        for (int r = 0; r < 4; r++) dst[tid + 256*r] = src[tid + 256*r];
    }
    if (tid < 192) {
        int r = tid / DF, d = tid - r * DF;
        xiT[d][r] = X[(I * 32 + h * 16 + r) * DF + d];
    }
    for (int u = tid; u < 384; u += 256) {
        int r = u / DF, d = u - r * DF;
        xjT[d][r] = X[(J * 32 + r) * DF + d];
    }
    __syncthreads();

    const int j = J * 32 + lane;
    float pj[DF];
#pragma unroll
    for (int d = 0; d < DF; d++) pj[d] = xjT[d][lane];

#pragma unroll
    for (int q = 0; q < 2; q++) {
        const int il = w + 8 * q;
        const int i  = I * 32 + h * 16 + il;
        float sim;
        if (i == j) {
            sim = -1e9f;
        } else {
            float k[DF];
#pragma unroll
            for (int d = 0; d < DF; d++) {
                float diff = pj[d] - xiT[d][il];
                float v = exp2f(-1.442695041f * fabsf(diff));
                k[d] = __uint_as_float((__float_as_uint(v) & 0xFFFFFFF0u)
                                       | (unsigned)d);
            }
#pragma unroll
            for (int p = 1; p < DF; p <<= 1) {
#pragma unroll
                for (int kk = p; kk >= 1; kk >>= 1) {
#pragma unroll
                    for (int jj = kk % p; jj <= DF - 1 - kk; jj += 2 * kk) {
#pragma unroll
                        for (int ii = 0; ii < kk; ii++) {
                            int a = ii + jj, c = ii + jj + kk;
                            if (c < DF && (a / (2 * p)) == (c / (2 * p))) {
                                float lo = fminf(k[a], k[c]);
                                float hi = fmaxf(k[a], k[c]);
                                k[a] = lo; k[c] = hi;
                            }
                        }
                    }
                }
            }
            float prev = 0.0f; sim = 0.0f;
            unsigned mask = (unsigned)(NMASK - 1);
#pragma unroll
            for (int p = 0; p < DF; p++) {
                unsigned kb = __float_as_uint(k[p]);
                float v = __uint_as_float(kb & 0xFFFFFFF0u);
                sim = fmaf(v - prev, caps[mask], sim);
                prev = v;
                mask &= ~(1u << (kb & 0xFu));
            }
        }
        tile[il][lane] = sim;
    }
    __syncthreads();

#pragma unroll
    for (int q = 0; q < 2; q++) {
        const int il = w + 8 * q;
        g_sims[(I * 32 + h * 16 + il) * NROWS + J * 32 + lane] = tile[il][lane];
    }
    if (I != J) {
        for (int u = tid; u < 512; u += 256) {
            int row2 = u >> 4, c = u & 15;
            g_sims[(J * 32 + row2) * NROWS + I * 32 + h * 16 + c] = tile[c][row2];
        }
    }
}

// ---------------------------------------------------------------------------
// tie-aware warp bitonic sort (desc by val, ties -> lower idx first)
// ---------------------------------------------------------------------------
__device__ __forceinline__ void warp_sort32_tie(float& val, int& idx, int lane)
{
#pragma unroll
    for (int kk = 2; kk <= 32; kk <<= 1) {
#pragma unroll
        for (int jj = kk >> 1; jj > 0; jj >>= 1) {
            float ov = __shfl_xor_sync(0xffffffffu, val, jj);
            int   oi = __shfl_xor_sync(0xffffffffu, idx, jj);
            bool lower   = (lane & jj) == 0;
            bool dirdesc = (lane & kk) == 0;
            bool takeMax = dirdesc ? lower : !lower;
            bool better  = (ov > val) || (ov == val && oi < idx);
            bool sw = takeMax ? better : !better;
            if (sw) { val = ov; idx = oi; }
        }
    }
}

// ---------------------------------------------------------------------------
// Kernel 4: exact radix-select top-32 + softmax vote. 1024 blocks x 256 thr.
// 3x 8-bit histogram passes find the 24-bit prefix of the 32nd-largest key;
// candidates (key>=prefix, ~32-40 of them) are compacted in index order and
// two warps sort/merge them with idx tiebreak (== jax top_k tie rule).
// ---------------------------------------------------------------------------
__global__ void __launch_bounds__(256)
topk_kernel(const int* __restrict__ y, float* __restrict__ out)
{
    __shared__ unsigned hist[256];
    __shared__ unsigned sh_prefix, sh_rank;
    __shared__ unsigned warp_cnt[8];
    __shared__ unsigned sh_total;
    __shared__ float cv[64];
    __shared__ int   ci[64];

    const int r    = blockIdx.x;
    const int tid  = threadIdx.x;
    const int lane = tid & 31, w = tid >> 5;

    // load 4 strided elements; monotone uint keys (desc float == desc uint)
    float v[4]; unsigned key[4];
#pragma unroll
    for (int g = 0; g < 4; g++) {
        int j = g * 256 + tid;
        float x = (j == r) ? -1e9f : g_sims[r * NROWS + j];
        v[g] = x;
        unsigned b = __float_as_uint(x);
        key[g] = (b & 0x80000000u) ? ~b : (b | 0x80000000u);
    }

    unsigned prefix = 0;      // resolved high bytes (right-aligned)
    unsigned rank   = KSEL;   // still needed within current prefix group

    for (int p = 0; p < 3; p++) {
        const int sh = 24 - 8 * p;
        hist[tid] = 0;
        __syncthreads();
#pragma unroll
        for (int g = 0; g < 4; g++) {
            bool active = (p == 0) || ((key[g] >> (sh + 8)) == prefix);
            if (active) atomicAdd(&hist[(key[g] >> sh) & 0xFFu], 1u);
        }
        __syncthreads();
        if (w == 0) {
            unsigned part = 0;
#pragma unroll
            for (int b = 0; b < 8; b++) part += hist[lane * 8 + b];
            // inclusive suffix sum across lanes (suf_l = sum of lanes >= l)
            unsigned suf = part;
#pragma unroll
            for (int off = 1; off < 32; off <<= 1) {
                unsigned t2 = __shfl_down_sync(0xffffffffu, suf, off);
                if (lane + off < 32) suf += t2;
            }
            unsigned above = __shfl_down_sync(0xffffffffu, suf, 1);
            unsigned mask  = __ballot_sync(0xffffffffu, suf >= rank);
            int lstar = 31 - __clz(mask);            // mask != 0 guaranteed
            if (lane == lstar) {
                unsigned run = (lstar == 31) ? 0u : above;  // count above group
                int cstar = lane * 8; unsigned histc = 0;
                for (int b = lane * 8 + 7; b >= lane * 8; b--) {
                    run += hist[b];
                    if (run >= rank) { cstar = b; histc = hist[b]; break; }
                }
                sh_prefix = (prefix << 8) | (unsigned)cstar;
                sh_rank   = rank - (run - histc);    // subtract strictly-greater
            }
        }
        __syncthreads();
        prefix = sh_prefix;
        rank   = sh_rank;
    }
    // prefix = top-24 bits of the 32nd-largest key; rank >= 1 within eq group

    // deterministic index-ordered compaction of candidates (key>>8 >= prefix)
    if (tid == 0) sh_total = 0;
    __syncthreads();
    for (int g = 0; g < 4; g++) {
        bool cand = (key[g] >> 8) >= prefix;
        unsigned bal = __ballot_sync(0xffffffffu, cand);
        if (lane == 0) warp_cnt[w] = __popc(bal);
        __syncthreads();
        unsigned base = sh_total;
        for (int ww = 0; ww < w; ww++) base += warp_cnt[ww];
        unsigned myoff = base + __popc(bal & ((1u << lane) - 1u));
        if (cand && myoff < 64) { cv[myoff] = v[g]; ci[myoff] = g * 256 + tid; }
        __syncthreads();
        if (tid == 0) {
            unsigned t2 = sh_total;
            for (int ww = 0; ww < 8; ww++) t2 += warp_cnt[ww];
            sh_total = t2;
        }
        __syncthreads();
    }
    unsigned total = sh_total;          // >= 32 by construction
    unsigned start = total < 64u ? total : 64u;
    for (int s = (int)start + tid; s < 64; s += 256) { cv[s] = -3e38f; ci[s] = 1 << 30; }
    __syncthreads();

    // sort the <=64 candidates: warps 0/1 sort halves, then merge in warp 0
    if (w < 2) {
        float sv = cv[w * 32 + lane];
        int   si = ci[w * 32 + lane];
        warp_sort32_tie(sv, si, lane);
        cv[w * 32 + lane] = sv;
        ci[w * 32 + lane] = si;
    }
    __syncthreads();

    if (w == 0) {
        float av = cv[lane];            int ai = ci[lane];
        float bv = cv[32 + (31 - lane)]; int bi = ci[32 + (31 - lane)];
        bool takeB = (bv > av) || (bv == av && bi < ai);
        float xv = takeB ? bv : av;
        int   xi = takeB ? bi : ai;
#pragma unroll
        for (int off = 16; off; off >>= 1) {   // bitonic clean, desc + tie
            float ov = __shfl_xor_sync(0xffffffffu, xv, off);
            int   oi = __shfl_xor_sync(0xffffffffu, xi, off);
            bool up = (lane & off) == 0;
            bool better = (ov > xv) || (ov == xv && oi < xi);
            bool take = up ? better : !better;
            if (take) { xv = ov; xi = oi; }
        }
        // lane t = t-th largest; softmax vote
        float vmax = __shfl_sync(0xffffffffu, xv, 0);
        float e = __expf((xv - vmax) * 2.0f);   // 1/TEMP = 2
        float s = e;
#pragma unroll
        for (int off = 16; off; off >>= 1) s += __shfl_xor_sync(0xffffffffu, s, off);
        float wgt = e / s;
        int label = y[xi];
#pragma unroll
        for (int cc = 0; cc < NCLS; cc++) {
            float vc = (label == cc) ? wgt : 0.0f;
#pragma unroll
            for (int off = 16; off; off >>= 1) vc += __shfl_xor_sync(0xffffffffu, vc, off);
            if (lane == 0) out[r * NCLS + cc] = vc;
        }
    }
}

// ---------------------------------------------------------------------------
extern "C" void kernel_launch(void* const* d_in, const int* in_sizes, int n_in,
                              void* d_out, int out_size)
{
    const float* X    = (const float*)d_in[0];
    const int*   y    = (const int*)  d_in[1];
    const float* w1   = (const float*)d_in[2];
    const float* b1   = (const float*)d_in[3];
    const float* w2   = (const float*)d_in[4];
    const float* b2   = (const float*)d_in[5];
    const float* lng  = (const float*)d_in[6];
    const float* lnb  = (const float*)d_in[7];
    const float* w3   = (const float*)d_in[8];
    const float* b3   = (const float*)d_in[9];
    const float* cw1  = (const float*)d_in[10];
    const float* cb1  = (const float*)d_in[11];
    const float* cw2  = (const float*)d_in[12];
    const float* cb2  = (const float*)d_in[13];
    float* out = (float*)d_out;

    enc_kernel<<<32, 32>>>(X, w1, b1, w2, b2, lng, lnb, w3, b3);
    capgen_kernel<<<1, 1024>>>(cw1, cb1, cw2, cb2, out);
    sym_kernel<<<1056, 256>>>(X);
    topk_kernel<<<1024, 256>>>(y, out);
}